// round 3
// baseline (speedup 1.0000x reference)
#include <cuda_runtime.h>
#include <stdint.h>
#include <math.h>

// Problem constants (SHAPE = (16,1,1024,1024), RATIO = 0.25)
#define N_TOTAL   16777216
#define N_VEC     (N_TOTAL / 4)
#define K_SEL     4194304
#define H1_BINS   8192       // bits [30:18] (sign always 0 since loss >= 0)
#define H2_BINS   262144     // bits [17:0]  -> exact value within coarse bucket
#define GRID_BIG  304
#define TPB_BIG   1024

// Scratch state (device globals -- no allocation allowed)
__device__ uint32_t g_scratch[N_TOTAL];   // loss as ordered uint32 bit patterns
__device__ uint32_t g_hist1[H1_BINS];
__device__ uint32_t g_hist2[H2_BINS];
__device__ uint32_t g_bstar;
__device__ uint32_t g_cAbove;
__device__ double   g_sumAbove;

__device__ __forceinline__ float bce_loss(float x, float t) {
    // max(x,0) - x*t + log1p(exp(-|x|)); always >= 0 for t in [0,1)
    float l = fmaxf(x, 0.0f) - x * t + log1pf(__expf(-fabsf(x)));
    return fmaxf(l, 0.0f);  // defensive: keep sign bit 0 so uint order == float order
}

// ---------------------------------------------------------------------------
// K0: zero the histograms + accumulator (must run every graph replay)
// ---------------------------------------------------------------------------
__global__ void zero_kernel() {
    int idx = blockIdx.x * blockDim.x + threadIdx.x;
    int stride = gridDim.x * blockDim.x;
    for (int i = idx; i < H2_BINS; i += stride) g_hist2[i] = 0u;
    for (int i = idx; i < H1_BINS; i += stride) g_hist1[i] = 0u;
    if (idx == 0) g_sumAbove = 0.0;
}

// ---------------------------------------------------------------------------
// K1: compute loss, write scratch, build coarse 8192-bin histogram
// ---------------------------------------------------------------------------
__device__ __forceinline__ void hist_add(uint32_t* sh, uint32_t v, unsigned lane) {
    uint32_t bin = v >> 18;                       // < 8192 for any non-negative float
    unsigned m = __match_any_sync(0xFFFFFFFFu, bin);  // warp-aggregate hot bins
    unsigned leader = __ffs(m) - 1u;
    if (lane == leader) atomicAdd(&sh[bin], (uint32_t)__popc(m));
}

__global__ void __launch_bounds__(TPB_BIG) loss_hist_kernel(
    const float* __restrict__ pred, const float* __restrict__ tgt) {
    __shared__ uint32_t sh[H1_BINS];              // 32 KB
    for (int i = threadIdx.x; i < H1_BINS; i += TPB_BIG) sh[i] = 0u;
    __syncthreads();

    unsigned lane = threadIdx.x & 31u;
    int tid = blockIdx.x * TPB_BIG + threadIdx.x;
    int stride = gridDim.x * TPB_BIG;
    const float4* p4 = (const float4*)pred;
    const float4* t4 = (const float4*)tgt;
    uint4* s4 = (uint4*)g_scratch;

    // N_VEC and stride are multiples of 32 -> loop trip count is warp-uniform,
    // so the full-mask __match_any_sync is legal.
    for (int i = tid; i < N_VEC; i += stride) {
        float4 p = p4[i];
        float4 t = t4[i];
        uint4 u;
        u.x = __float_as_uint(bce_loss(p.x, t.x));
        u.y = __float_as_uint(bce_loss(p.y, t.y));
        u.z = __float_as_uint(bce_loss(p.z, t.z));
        u.w = __float_as_uint(bce_loss(p.w, t.w));
        s4[i] = u;
        hist_add(sh, u.x, lane);
        hist_add(sh, u.y, lane);
        hist_add(sh, u.z, lane);
        hist_add(sh, u.w, lane);
    }
    __syncthreads();
    for (int i = threadIdx.x; i < H1_BINS; i += TPB_BIG) {
        uint32_t c = sh[i];
        if (c) atomicAdd(&g_hist1[i], c);
    }
}

// ---------------------------------------------------------------------------
// K2: single block -- find coarse bucket b* containing the K-th largest
// ---------------------------------------------------------------------------
__global__ void __launch_bounds__(1024) select_bucket_kernel() {
    __shared__ uint32_t csum[1024];
    __shared__ uint32_t wsum[32];
    int t = threadIdx.x;
    uint32_t s = 0;
    int base = t * 8;                    // 8 bins per thread
#pragma unroll
    for (int j = 0; j < 8; j++) s += g_hist1[base + j];
    csum[t] = s;
    uint32_t ws = s;
#pragma unroll
    for (int o = 16; o; o >>= 1) ws += __shfl_down_sync(0xFFFFFFFFu, ws, o);
    if ((t & 31) == 0) wsum[t >> 5] = ws;
    __syncthreads();

    if (t == 0) {
        uint32_t cum = 0;
        int w = 31;
        for (; w >= 0; w--) { if (cum + wsum[w] >= (uint32_t)K_SEL) break; cum += wsum[w]; }
        int c = w * 32 + 31;
        for (; c >= w * 32; c--) { if (cum + csum[c] >= (uint32_t)K_SEL) break; cum += csum[c]; }
        int b = c * 8 + 7;
        for (; b >= c * 8; b--) {
            uint32_t h = g_hist1[b];
            if (cum + h >= (uint32_t)K_SEL) break;
            cum += h;
        }
        g_bstar = (uint32_t)b;
        g_cAbove = cum;                  // count of elements strictly above bucket b*
    }
}

// ---------------------------------------------------------------------------
// K3: sum elements above bucket b*; exact-value histogram inside bucket b*
// ---------------------------------------------------------------------------
__global__ void __launch_bounds__(TPB_BIG) refine_kernel() {
    const uint32_t bstar = g_bstar;
    int tid = blockIdx.x * TPB_BIG + threadIdx.x;
    int stride = gridDim.x * TPB_BIG;
    const uint4* s4 = (const uint4*)g_scratch;
    float fs = 0.0f;

    for (int i = tid; i < N_VEC; i += stride) {
        uint4 u = s4[i];
        uint32_t v, b;
        v = u.x; b = v >> 18;
        if (b > bstar) fs += __uint_as_float(v);
        else if (b == bstar) atomicAdd(&g_hist2[v & 0x3FFFFu], 1u);
        v = u.y; b = v >> 18;
        if (b > bstar) fs += __uint_as_float(v);
        else if (b == bstar) atomicAdd(&g_hist2[v & 0x3FFFFu], 1u);
        v = u.z; b = v >> 18;
        if (b > bstar) fs += __uint_as_float(v);
        else if (b == bstar) atomicAdd(&g_hist2[v & 0x3FFFFu], 1u);
        v = u.w; b = v >> 18;
        if (b > bstar) fs += __uint_as_float(v);
        else if (b == bstar) atomicAdd(&g_hist2[v & 0x3FFFFu], 1u);
    }

    __shared__ float wpart[32];
#pragma unroll
    for (int o = 16; o; o >>= 1) fs += __shfl_down_sync(0xFFFFFFFFu, fs, o);
    if ((threadIdx.x & 31) == 0) wpart[threadIdx.x >> 5] = fs;
    __syncthreads();
    if (threadIdx.x == 0) {
        double d = 0.0;
#pragma unroll
        for (int i = 0; i < 32; i++) d += (double)wpart[i];
        atomicAdd(&g_sumAbove, d);
    }
}

// ---------------------------------------------------------------------------
// K4: single block -- exact threshold, tie handling, final mean
// ---------------------------------------------------------------------------
__global__ void __launch_bounds__(1024) finalize_kernel(float* __restrict__ out) {
    __shared__ uint32_t csum[1024];
    __shared__ uint32_t wsum[32];
    __shared__ double   dpart[32];
    __shared__ uint32_t s_binT, s_need;

    int t = threadIdx.x;
    const uint32_t bstar = g_bstar;
    const uint32_t rem = (uint32_t)K_SEL - g_cAbove;   // 1 <= rem <= hist1[b*]
    int base = t * 256;                                // 256 bins per thread

    uint32_t s = 0;
    for (int j = 0; j < 256; j++) s += g_hist2[base + j];
    csum[t] = s;
    uint32_t ws = s;
#pragma unroll
    for (int o = 16; o; o >>= 1) ws += __shfl_down_sync(0xFFFFFFFFu, ws, o);
    if ((t & 31) == 0) wsum[t >> 5] = ws;
    __syncthreads();

    if (t == 0) {
        uint32_t cum = 0;
        int w = 31;
        for (; w >= 0; w--) { if (cum + wsum[w] >= rem) break; cum += wsum[w]; }
        int c = w * 32 + 31;
        for (; c >= w * 32; c--) { if (cum + csum[c] >= rem) break; cum += csum[c]; }
        int b = c * 256 + 255;
        for (; b >= c * 256; b--) {
            uint32_t h = g_hist2[b];
            if (cum + h >= rem) break;
            cum += h;
        }
        s_binT = (uint32_t)b;
        s_need = rem - cum;              // # of elements equal to threshold to include
    }
    __syncthreads();

    const uint32_t binT = s_binT;
    // Sum of in-bucket elements strictly above threshold: bins are exact values.
    double ds = 0.0;
    for (int j = 0; j < 256; j++) {
        uint32_t b = (uint32_t)(base + j);
        if (b > binT) {
            uint32_t h = g_hist2[b];
            if (h) ds += (double)h * (double)__uint_as_float((bstar << 18) | b);
        }
    }
#pragma unroll
    for (int o = 16; o; o >>= 1) ds += __shfl_down_sync(0xFFFFFFFFu, ds, o);
    if ((t & 31) == 0) dpart[t >> 5] = ds;
    __syncthreads();

    if (t == 0) {
        double tot = g_sumAbove;
#pragma unroll
        for (int i = 0; i < 32; i++) tot += dpart[i];
        float tval = __uint_as_float((bstar << 18) | binT);
        tot += (double)s_need * (double)tval;
        out[0] = (float)(tot / (double)K_SEL);
    }
}

// ---------------------------------------------------------------------------
extern "C" void kernel_launch(void* const* d_in, const int* in_sizes, int n_in,
                              void* d_out, int out_size) {
    (void)in_sizes; (void)n_in; (void)out_size;
    const float* pred = (const float*)d_in[0];
    const float* tgt  = (const float*)d_in[1];
    float* out = (float*)d_out;

    zero_kernel<<<256, 1024>>>();
    loss_hist_kernel<<<GRID_BIG, TPB_BIG>>>(pred, tgt);
    select_bucket_kernel<<<1, 1024>>>();
    refine_kernel<<<GRID_BIG, TPB_BIG>>>();
    finalize_kernel<<<1, 1024>>>(out);
}